// round 14
// baseline (speedup 1.0000x reference)
#include <cuda_runtime.h>
#include <cuda_fp16.h>
#include <cstdint>

#define BB 16
#define NN 2048
#define DD 768
#define ROWS (BB*NN)

#define KC 64                  // k elems per chunk (128B rows)
#define NCH (DD/KC)            // 12 chunks per tile item
#define HB 8                   // batches per half
#define HITEMS (HB*16*16)      // 2048 items per half
#define GRID 296               // 148 SMs x 2 CTA/SM (persistent)
#define NSTAGE 3
#define SUB 16384              // one 128-row x 128B sub-buffer (swizzled)
#define STAGE (2*SUB)          // A, B
#define SMEM_DYN (NSTAGE*STAGE + 128*8 + 128*4)   // 99840
#define CAP 64
#define MARGIN 4e-4f

// ---- scratch (allocation-free rule: __device__ globals) --------------------
__device__ __align__(16) __half g_Qh[(size_t)ROWS*DD];  // fp16(q/||q||)
__device__ __align__(16) __half g_Ch[(size_t)ROWS*DD];  // fp16(c/||c||)
__device__ float g_invq[ROWS];
__device__ float g_invc[ROWS];
__device__ unsigned long long g_gmax[ROWS];
__device__ int   g_cnt[ROWS];
__device__ int   g_cand[(size_t)ROWS*CAP];

// ---------------------------------------------------------------------------
__device__ __forceinline__ uint32_t smem_u32(const void* p) {
    uint32_t a;
    asm("{ .reg .u64 t; cvta.to.shared.u64 t, %1; cvt.u32.u64 %0, t; }" : "=r"(a) : "l"(p));
    return a;
}
// swizzled offset in a 128-row x 128B sub-buffer: piece (16B) XOR row&7.
// 8 consecutive rows with fixed piece hit 8 distinct 16B bank groups.
__device__ __forceinline__ uint32_t swoff(int row, int piece) {
    return (uint32_t)(row * 128 + ((piece ^ (row & 7)) << 4));
}
__device__ __forceinline__ unsigned long long packsc(float v, int col) {
    uint32_t b = __float_as_uint(v);
    uint32_t key = (b & 0x80000000u) ? ~b : (b | 0x80000000u);
    return ((unsigned long long)key << 32) | (uint32_t)(2047 - col);
}
__device__ __forceinline__ float unpack_score(unsigned long long p) {
    uint32_t key = (uint32_t)(p >> 32);
    uint32_t fb = (key & 0x80000000u) ? (key & 0x7FFFFFFFu) : ~key;
    return __uint_as_float(fb);
}

#define LDSM4(r, addr) \
    asm volatile("ldmatrix.sync.aligned.m8n8.x4.shared.b16 {%0,%1,%2,%3}, [%4];" \
        : "=r"((r)[0]), "=r"((r)[1]), "=r"((r)[2]), "=r"((r)[3]) : "r"(addr))

#define MMA16816(d, a, b) \
    asm volatile("mma.sync.aligned.m16n8k16.row.col.f32.f16.f16.f32 " \
        "{%0,%1,%2,%3}, {%4,%5,%6,%7}, {%8,%9}, {%0,%1,%2,%3};" \
        : "+f"((d)[0]), "+f"((d)[1]), "+f"((d)[2]), "+f"((d)[3]) \
        : "r"((a)[0]), "r"((a)[1]), "r"((a)[2]), "r"((a)[3]), "r"((b)[0]), "r"((b)[1]))

#define CP_ASYNC16(dst, src) \
    asm volatile("cp.async.cg.shared.global [%0], [%1], 16;" :: "r"(dst), "l"(src))
#define CP_COMMIT() asm volatile("cp.async.commit_group;" ::: "memory")
#define CP_WAIT1()  asm volatile("cp.async.wait_group 1;" ::: "memory")

// ---------------------------------------------------------------------------
// Prepass (per half): warp per row, both sides. grid (2*HB*NN)/8 blocks.
// ---------------------------------------------------------------------------
__global__ __launch_bounds__(256) void prep_kernel(const float* __restrict__ Qi,
                                                   const float* __restrict__ Ci,
                                                   int b0) {
    const int gwarp = blockIdx.x * 8 + (threadIdx.x >> 5);
    const int lane = threadIdx.x & 31;
    const bool isC = gwarp >= HB * NN;
    const int r = b0 * NN + (gwarp & (HB * NN - 1));
    const float4* src = (const float4*)((isC ? Ci : Qi) + (size_t)r * DD);
    float4 v[6]; float ss = 0.f;
#pragma unroll
    for (int q = 0; q < 6; q++) {
        v[q] = src[lane + 32 * q];
        ss += v[q].x * v[q].x + v[q].y * v[q].y + v[q].z * v[q].z + v[q].w * v[q].w;
    }
#pragma unroll
    for (int o = 16; o > 0; o >>= 1) ss += __shfl_xor_sync(~0u, ss, o);
    float inv = rsqrtf(ss);
    inv = inv * (1.5f - 0.5f * ss * inv * inv);   // Newton -> ~fp32 exact
    __half* dst = (isC ? g_Ch : g_Qh) + (size_t)r * DD;
#pragma unroll
    for (int q = 0; q < 6; q++) {
        __half2 h0 = __floats2half2_rn(v[q].x * inv, v[q].y * inv);
        __half2 h1 = __floats2half2_rn(v[q].z * inv, v[q].w * inv);
        uint2 u; u.x = *(uint32_t*)&h0; u.y = *(uint32_t*)&h1;
        ((uint2*)dst)[lane + 32 * q] = u;
    }
    if (lane == 0) {
        if (isC) g_invc[r] = inv;
        else { g_invq[r] = inv; g_cnt[r] = 0; g_gmax[r] = 0ull; }
    }
}

// ---------------------------------------------------------------------------
// Persistent fp16 approx GEMM + margin candidates. KC=64 chunks, 3 stages.
// 296 CTAs, 256 thr, 2 CTA/SM. 2048 items per half, strided.
// ---------------------------------------------------------------------------
__global__ __launch_bounds__(256, 2) void gemm_kernel(int b0) {
    extern __shared__ __align__(1024) unsigned char smem[];
    const uint32_t sb = smem_u32(smem);
    unsigned long long* table = (unsigned long long*)(smem + NSTAGE * STAGE);
    float* tableF = (float*)(smem + NSTAGE * STAGE + 128 * 8);

    const int cta = blockIdx.x;
    const int tid = threadIdx.x, wid = tid >> 5, lane = tid & 31;
    const int wm = wid & 1, wn = wid >> 1;

    const int nit = (HITEMS - cta + GRID - 1) / GRID;
    const int nch_tot = nit * NCH;

    if (tid < 128) table[tid] = 0ull;
    __syncthreads();

    float acc[4][4][4];
#pragma unroll
    for (int i = 0; i < 4; i++)
#pragma unroll
        for (int j = 0; j < 4; j++)
#pragma unroll
            for (int c = 0; c < 4; c++) acc[i][j][c] = 0.f;

    // per-chunk loads: A 1024 pieces + B 1024 pieces, 256 thr -> 4+4 each
    auto issue_chunk = [&](int f, int stage_idx) {
        const int il = f / NCH, kc = f - il * NCH;
        const int item = cta + il * GRID;
        const int b = b0 + (item >> 8), mt = (item >> 4) & 15, nt = item & 15;
        const uint32_t stage = sb + (uint32_t)stage_idx * STAGE;
        const __half* abase = g_Qh + (size_t)(b * NN + mt * 128) * DD + kc * KC;
        const __half* bbase = g_Ch + (size_t)(b * NN + nt * 128) * DD + kc * KC;
#pragma unroll
        for (int pp = 0; pp < 4; pp++) {
            const int p = tid * 4 + pp;
            const int row = p >> 3, q = p & 7;
            const uint32_t so = swoff(row, q);
            CP_ASYNC16(stage + so,       abase + (size_t)row * DD + q * 8);
            CP_ASYNC16(stage + SUB + so, bbase + (size_t)row * DD + q * 8);
        }
        CP_COMMIT();
    };

    // prologue: chunks 0,1 into stages 0,1
    issue_chunk(0, 0); issue_chunk(1, 1);

    int cs = 0, is = 2;   // consume / issue stage (mod 3, rolling)
    for (int f = 0; f < nch_tot; f++) {
        CP_WAIT1();
        __syncthreads();
        const uint32_t abase = sb + (uint32_t)cs * STAGE;
#pragma unroll
        for (int kk = 0; kk < 4; kk++) {       // four k16 sub-steps per chunk
            uint32_t ah[4][4], bh[4][2];
            const int lr = lane & 15, lp = lane >> 4;
#pragma unroll
            for (int i = 0; i < 4; i++)
                LDSM4(ah[i], abase + swoff(wm * 64 + i * 16 + lr, kk * 2 + lp));
#pragma unroll
            for (int jp = 0; jp < 2; jp++) {
                const int nrow = wn * 32 + (jp * 2 + (lane >> 4)) * 8 + (lane & 7);
                const int piece = kk * 2 + ((lane >> 3) & 1);
                uint32_t r4[4];
                LDSM4(r4, abase + SUB + swoff(nrow, piece));
                bh[jp*2][0]=r4[0]; bh[jp*2][1]=r4[1]; bh[jp*2+1][0]=r4[2]; bh[jp*2+1][1]=r4[3];
            }
#pragma unroll
            for (int i = 0; i < 4; i++)
#pragma unroll
                for (int j = 0; j < 4; j++)
                    MMA16816(acc[i][j], ah[i], bh[j]);
        }
        if (f + 2 < nch_tot) { issue_chunk(f + 2, is); is = (is == 2) ? 0 : is + 1; }
        cs = (cs == 2) ? 0 : cs + 1;

        const int il = f / NCH;
        if (f - il * NCH == NCH - 1) {
            const int item = cta + il * GRID;
            const int b = b0 + (item >> 8), mt = (item >> 4) & 15, nt = item & 15;
            const int qrow0 = b * NN + mt * 128;
            const int colbase = nt * 128 + wn * 32 + (lane & 3) * 2;
            // phase 1: per-row tile max into smem table
#pragma unroll
            for (int i = 0; i < 4; i++)
#pragma unroll
                for (int half = 0; half < 2; half++) {
                    float bv = -3.0e38f; int bc = 0;
#pragma unroll
                    for (int j = 0; j < 4; j++) {
                        const int c0 = colbase + j * 8;
                        float v0 = acc[i][j][half * 2 + 0];
                        if (v0 > bv) { bv = v0; bc = c0; }
                        float v1 = acc[i][j][half * 2 + 1];
                        if (v1 > bv) { bv = v1; bc = c0 + 1; }
                    }
#pragma unroll
                    for (int off = 1; off < 4; off <<= 1) {
                        float ov = __shfl_xor_sync(~0u, bv, off);
                        int   oc = __shfl_xor_sync(~0u, bc, off);
                        if (ov > bv || (ov == bv && oc < bc)) { bv = ov; bc = oc; }
                    }
                    if ((lane & 3) == 0) {
                        const int rloc = wm * 64 + i * 16 + half * 8 + (lane >> 2);
                        atomicMax(&table[rloc], packsc(bv, bc));
                    }
                }
            __syncthreads();
            // merge with global running row max -> cut
            if (tid < 128) {
                unsigned long long loc = table[tid];
                unsigned long long old = atomicMax(&g_gmax[qrow0 + tid], loc);
                if (old > loc) loc = old;
                tableF[tid] = unpack_score(loc) - MARGIN;
            }
            __syncthreads();
            // phase 2: append candidates >= cut
#pragma unroll
            for (int i = 0; i < 4; i++)
#pragma unroll
                for (int half = 0; half < 2; half++) {
                    const int rloc = wm * 64 + i * 16 + half * 8 + (lane >> 2);
                    const float cut = tableF[rloc];
                    const int rg = qrow0 + rloc;
#pragma unroll
                    for (int j = 0; j < 4; j++)
#pragma unroll
                        for (int c = 0; c < 2; c++) {
                            float v = acc[i][j][half * 2 + c];
                            if (v >= cut) {
                                int slot = atomicAdd(&g_cnt[rg], 1);
                                if (slot < CAP)
                                    g_cand[(size_t)rg * CAP + slot] = colbase + j * 8 + c;
                            }
                        }
                }
            __syncthreads();
            if (tid < 128) table[tid] = 0ull;
            // next table use is >= 12 chunks away, separated by syncs.
#pragma unroll
            for (int i = 0; i < 4; i++)
#pragma unroll
                for (int j = 0; j < 4; j++)
#pragma unroll
                    for (int c = 0; c < 4; c++) acc[i][j][c] = 0.f;
        }
    }
}

// ---------------------------------------------------------------------------
// Exact rescore + blend (per half): warp per row. grid HB*NN/8 blocks.
// out layout: [reuse_map (B*N)] [reuse_input (B*N*D)] [reuse_value (B*N*D)]
// ---------------------------------------------------------------------------
__global__ __launch_bounds__(256) void rescore_blend_kernel(
    const float* __restrict__ Qi, const float* __restrict__ Qv,
    const float* __restrict__ Ci, const float* __restrict__ Cv,
    const float* __restrict__ thr_raw, float* __restrict__ out, int b0) {
    const int r = b0 * NN + blockIdx.x * 8 + (threadIdx.x >> 5);
    const int lane = threadIdx.x & 31;
    const int b = r >> 11;
    const int n = r & (NN - 1);

    const float4* q4p = (const float4*)(Qi + (size_t)r * DD);
    float4 q4[6];
#pragma unroll
    for (int q = 0; q < 6; q++) q4[q] = q4p[lane + 32 * q];

    int cnt = g_cnt[r]; if (cnt > CAP) cnt = CAP;
    const float invq = g_invq[r];
    unsigned long long best = 0ull;
    for (int ci = 0; ci < cnt; ci++) {
        const int idx = g_cand[(size_t)r * CAP + ci];
        const float4* crow = (const float4*)(Ci + ((size_t)(b * NN + idx)) * DD);
        float s = 0.f;
#pragma unroll
        for (int q = 0; q < 6; q++) {
            float4 cv = crow[lane + 32 * q];
            s += cv.x * q4[q].x + cv.y * q4[q].y + cv.z * q4[q].z + cv.w * q4[q].w;
        }
#pragma unroll
        for (int o = 16; o > 0; o >>= 1) s += __shfl_xor_sync(~0u, s, o);
        unsigned long long p = packsc(s * invq * g_invc[b * NN + idx], idx);
        if (p > best) best = p;       // identical on all lanes
    }
    const float score = unpack_score(best);
    const int idx = 2047 - (int)(uint32_t)(best & 0xFFFFFFFFull);
    const float thr = 1.f / (1.f + expf(-thr_raw[n]));
    const float rm  = 1.f / (1.f + expf(-40.f * (score - thr)));
    const float om  = 1.f - rm;

    const float4* qv = (const float4*)(Qv + (size_t)r * DD);
    const float4* cb = (const float4*)(Ci + ((size_t)b * NN + idx) * DD);
    const float4* cv = (const float4*)(Cv + ((size_t)b * NN + idx) * DD);
    float4* oi = (float4*)(out + ROWS + (size_t)r * DD);
    float4* ov = (float4*)(out + ROWS + (size_t)ROWS * DD + (size_t)r * DD);
#pragma unroll
    for (int q = 0; q < 6; q++) {
        const int e = lane + 32 * q;
        float4 a = q4[q], c = cb[e];
        oi[e] = make_float4(om * a.x + rm * c.x, om * a.y + rm * c.y,
                            om * a.z + rm * c.z, om * a.w + rm * c.w);
        float4 av = qv[e], cc = cv[e];
        ov[e] = make_float4(om * av.x + rm * cc.x, om * av.y + rm * cc.y,
                            om * av.z + rm * cc.z, om * av.w + rm * cc.w);
    }
    if (lane == 0) out[r] = rm;
}

// ---------------------------------------------------------------------------
// Host: half-granular software pipeline via fork/join events.
// prep(h1) overlaps gemm(h0); rescore(h0) overlaps gemm(h1).
// ---------------------------------------------------------------------------
static cudaStream_t sP = nullptr, sR = nullptr;
static cudaEvent_t  eFork, eJoin, eP0, eP1, eG0, eG1;

extern "C" void kernel_launch(void* const* d_in, const int* in_sizes, int n_in,
                              void* d_out, int out_size) {
    const float* Qi = (const float*)d_in[0];
    const float* Qv = (const float*)d_in[1];
    const float* Ci = (const float*)d_in[2];
    const float* Cv = (const float*)d_in[3];
    const float* Th = (const float*)d_in[4];
    float* out = (float*)d_out;

    if (sP == nullptr) {
        cudaStreamCreateWithFlags(&sP, cudaStreamNonBlocking);
        cudaStreamCreateWithFlags(&sR, cudaStreamNonBlocking);
        cudaEventCreateWithFlags(&eFork, cudaEventDisableTiming);
        cudaEventCreateWithFlags(&eJoin, cudaEventDisableTiming);
        cudaEventCreateWithFlags(&eP0, cudaEventDisableTiming);
        cudaEventCreateWithFlags(&eP1, cudaEventDisableTiming);
        cudaEventCreateWithFlags(&eG0, cudaEventDisableTiming);
        cudaEventCreateWithFlags(&eG1, cudaEventDisableTiming);
        cudaFuncSetAttribute(gemm_kernel,
                             cudaFuncAttributeMaxDynamicSharedMemorySize, SMEM_DYN);
    }

    cudaEventRecord(eFork, 0);
    cudaStreamWaitEvent(sP, eFork, 0);

    // prep halves on sP
    prep_kernel<<<(2 * HB * NN) / 8, 256, 0, sP>>>(Qi, Ci, 0);
    cudaEventRecord(eP0, sP);
    prep_kernel<<<(2 * HB * NN) / 8, 256, 0, sP>>>(Qi, Ci, HB);
    cudaEventRecord(eP1, sP);

    // gemm halves on main
    cudaStreamWaitEvent(0, eP0, 0);
    gemm_kernel<<<GRID, 256, SMEM_DYN>>>(0);
    cudaEventRecord(eG0, 0);
    cudaStreamWaitEvent(0, eP1, 0);
    gemm_kernel<<<GRID, 256, SMEM_DYN>>>(HB);
    cudaEventRecord(eG1, 0);

    // rescore halves on sR
    cudaStreamWaitEvent(sR, eG0, 0);
    rescore_blend_kernel<<<(HB * NN) / 8, 256, 0, sR>>>(Qi, Qv, Ci, Cv, Th, out, 0);
    cudaStreamWaitEvent(sR, eG1, 0);
    rescore_blend_kernel<<<(HB * NN) / 8, 256, 0, sR>>>(Qi, Qv, Ci, Cv, Th, out, HB);
    cudaEventRecord(eJoin, sR);
    cudaStreamWaitEvent(0, eJoin, 0);
}

// round 16
// speedup vs baseline: 1.0041x; 1.0041x over previous
#include <cuda_runtime.h>
#include <cuda_fp16.h>
#include <cstdint>

#define BB 16
#define NN 2048
#define DD 768
#define ROWS (BB*NN)

#define KC 64                  // k elems per chunk (128B rows)
#define NCH (DD/KC)            // 12 chunks per tile item
#define HB 8                   // batches per half
#define HITEMS (HB*16*16)      // 2048 items per half
#define GRID 296               // 148 SMs x 2 CTA/SM (persistent)
#define NSTAGE 3
#define SUB 16384              // one 128-row x 128B sub-buffer (swizzled)
#define STAGE (2*SUB)          // A, B
#define SMEM_DYN (NSTAGE*STAGE + 128*8 + 128*4)   // 99840
#define CAP 64
#define MARGIN 2e-3f

// ---- scratch (allocation-free rule: __device__ globals) --------------------
__device__ __align__(16) __half g_Qh[(size_t)ROWS*DD];  // fp16(q/||q||)
__device__ __align__(16) __half g_Ch[(size_t)ROWS*DD];  // fp16(c/||c||)
__device__ float g_invq[ROWS];
__device__ float g_invc[ROWS];
__device__ unsigned long long g_gmax[ROWS];
__device__ int   g_cnt[ROWS];
__device__ int   g_cand[(size_t)ROWS*CAP];

// ---------------------------------------------------------------------------
__device__ __forceinline__ uint32_t smem_u32(const void* p) {
    uint32_t a;
    asm("{ .reg .u64 t; cvta.to.shared.u64 t, %1; cvt.u32.u64 %0, t; }" : "=r"(a) : "l"(p));
    return a;
}
// swizzled offset in a 128-row x 128B sub-buffer: piece (16B) XOR row&7.
__device__ __forceinline__ uint32_t swoff(int row, int piece) {
    return (uint32_t)(row * 128 + ((piece ^ (row & 7)) << 4));
}
__device__ __forceinline__ unsigned long long packsc(float v, int col) {
    uint32_t b = __float_as_uint(v);
    uint32_t key = (b & 0x80000000u) ? ~b : (b | 0x80000000u);
    return ((unsigned long long)key << 32) | (uint32_t)(2047 - col);
}
__device__ __forceinline__ float unpack_score(unsigned long long p) {
    uint32_t key = (uint32_t)(p >> 32);
    uint32_t fb = (key & 0x80000000u) ? (key & 0x7FFFFFFFu) : ~key;
    return __uint_as_float(fb);
}

#define LDSM4(r, addr) \
    asm volatile("ldmatrix.sync.aligned.m8n8.x4.shared.b16 {%0,%1,%2,%3}, [%4];" \
        : "=r"((r)[0]), "=r"((r)[1]), "=r"((r)[2]), "=r"((r)[3]) : "r"(addr))

// fp16-accumulate HMMA: d(2x half2) = a(4) x b(2) + d
#define MMAH(d, a, b) \
    asm volatile("mma.sync.aligned.m16n8k16.row.col.f16.f16.f16.f16 " \
        "{%0,%1}, {%2,%3,%4,%5}, {%6,%7}, {%0,%1};" \
        : "+r"((d)[0]), "+r"((d)[1]) \
        : "r"((a)[0]), "r"((a)[1]), "r"((a)[2]), "r"((a)[3]), "r"((b)[0]), "r"((b)[1]))

#define CP_ASYNC16(dst, src) \
    asm volatile("cp.async.cg.shared.global [%0], [%1], 16;" :: "r"(dst), "l"(src))
#define CP_COMMIT() asm volatile("cp.async.commit_group;" ::: "memory")
#define CP_WAIT1()  asm volatile("cp.async.wait_group 1;" ::: "memory")

// ---------------------------------------------------------------------------
// Prepass (per half): warp per row, both sides. grid (2*HB*NN)/8 blocks.
// ---------------------------------------------------------------------------
__global__ __launch_bounds__(256) void prep_kernel(const float* __restrict__ Qi,
                                                   const float* __restrict__ Ci,
                                                   int b0) {
    const int gwarp = blockIdx.x * 8 + (threadIdx.x >> 5);
    const int lane = threadIdx.x & 31;
    const bool isC = gwarp >= HB * NN;
    const int r = b0 * NN + (gwarp & (HB * NN - 1));
    const float4* src = (const float4*)((isC ? Ci : Qi) + (size_t)r * DD);
    float4 v[6]; float ss = 0.f;
#pragma unroll
    for (int q = 0; q < 6; q++) {
        v[q] = src[lane + 32 * q];
        ss += v[q].x * v[q].x + v[q].y * v[q].y + v[q].z * v[q].z + v[q].w * v[q].w;
    }
#pragma unroll
    for (int o = 16; o > 0; o >>= 1) ss += __shfl_xor_sync(~0u, ss, o);
    float inv = rsqrtf(ss);
    inv = inv * (1.5f - 0.5f * ss * inv * inv);   // Newton -> ~fp32 exact
    __half* dst = (isC ? g_Ch : g_Qh) + (size_t)r * DD;
#pragma unroll
    for (int q = 0; q < 6; q++) {
        __half2 h0 = __floats2half2_rn(v[q].x * inv, v[q].y * inv);
        __half2 h1 = __floats2half2_rn(v[q].z * inv, v[q].w * inv);
        uint2 u; u.x = *(uint32_t*)&h0; u.y = *(uint32_t*)&h1;
        ((uint2*)dst)[lane + 32 * q] = u;
    }
    if (lane == 0) {
        if (isC) g_invc[r] = inv;
        else { g_invq[r] = inv; g_cnt[r] = 0; g_gmax[r] = 0ull; }
    }
}

// ---------------------------------------------------------------------------
// Persistent fp16 (fp16-accum) approx GEMM + margin candidates.
// KC=64 chunks, 3 stages, 296 CTAs, 256 thr. __maxnreg__(104) keeps
// 2 CTA/SM (53K regs) with ~11K regs spare so prep/rescore blocks can
// co-schedule on the same SMs.
// ---------------------------------------------------------------------------
__global__ void __maxnreg__(104) gemm_kernel(int b0) {
    extern __shared__ __align__(1024) unsigned char smem[];
    const uint32_t sb = smem_u32(smem);
    unsigned long long* table = (unsigned long long*)(smem + NSTAGE * STAGE);
    float* tableF = (float*)(smem + NSTAGE * STAGE + 128 * 8);

    const int cta = blockIdx.x;
    const int tid = threadIdx.x, wid = tid >> 5, lane = tid & 31;
    const int wm = wid & 1, wn = wid >> 1;

    const int nit = (HITEMS - cta + GRID - 1) / GRID;
    const int nch_tot = nit * NCH;

    if (tid < 128) table[tid] = 0ull;
    __syncthreads();

    uint32_t acc[4][4][2];   // fp16x2 accumulators, 64x32 warp tile
#pragma unroll
    for (int i = 0; i < 4; i++)
#pragma unroll
        for (int j = 0; j < 4; j++) { acc[i][j][0] = 0u; acc[i][j][1] = 0u; }

    auto issue_chunk = [&](int f, int stage_idx) {
        const int il = f / NCH, kc = f - il * NCH;
        const int item = cta + il * GRID;
        const int b = b0 + (item >> 8), mt = (item >> 4) & 15, nt = item & 15;
        const uint32_t stage = sb + (uint32_t)stage_idx * STAGE;
        const __half* abase = g_Qh + (size_t)(b * NN + mt * 128) * DD + kc * KC;
        const __half* bbase = g_Ch + (size_t)(b * NN + nt * 128) * DD + kc * KC;
#pragma unroll
        for (int pp = 0; pp < 4; pp++) {
            const int p = tid * 4 + pp;
            const int row = p >> 3, q = p & 7;
            const uint32_t so = swoff(row, q);
            CP_ASYNC16(stage + so,       abase + (size_t)row * DD + q * 8);
            CP_ASYNC16(stage + SUB + so, bbase + (size_t)row * DD + q * 8);
        }
        CP_COMMIT();
    };

    issue_chunk(0, 0); issue_chunk(1, 1);

    int cs = 0, is = 2;   // consume / issue stage (mod 3, rolling)
    for (int f = 0; f < nch_tot; f++) {
        CP_WAIT1();
        __syncthreads();
        const uint32_t abase = sb + (uint32_t)cs * STAGE;
#pragma unroll
        for (int kk = 0; kk < 4; kk++) {       // four k16 sub-steps per chunk
            uint32_t ah[4][4], bh[4][2];
            const int lr = lane & 15, lp = lane >> 4;
#pragma unroll
            for (int i = 0; i < 4; i++)
                LDSM4(ah[i], abase + swoff(wm * 64 + i * 16 + lr, kk * 2 + lp));
#pragma unroll
            for (int jp = 0; jp < 2; jp++) {
                const int nrow = wn * 32 + (jp * 2 + (lane >> 4)) * 8 + (lane & 7);
                const int piece = kk * 2 + ((lane >> 3) & 1);
                uint32_t r4[4];
                LDSM4(r4, abase + SUB + swoff(nrow, piece));
                bh[jp*2][0]=r4[0]; bh[jp*2][1]=r4[1]; bh[jp*2+1][0]=r4[2]; bh[jp*2+1][1]=r4[3];
            }
#pragma unroll
            for (int i = 0; i < 4; i++)
#pragma unroll
                for (int j = 0; j < 4; j++)
                    MMAH(acc[i][j], ah[i], bh[j]);
        }
        if (f + 2 < nch_tot) { issue_chunk(f + 2, is); is = (is == 2) ? 0 : is + 1; }
        cs = (cs == 2) ? 0 : cs + 1;

        const int il = f / NCH;
        if (f - il * NCH == NCH - 1) {
            const int item = cta + il * GRID;
            const int b = b0 + (item >> 8), mt = (item >> 4) & 15, nt = item & 15;
            const int qrow0 = b * NN + mt * 128;
            const int colbase = nt * 128 + wn * 32 + (lane & 3) * 2;
            // phase 1: per-row tile max into smem table
#pragma unroll
            for (int i = 0; i < 4; i++)
#pragma unroll
                for (int half = 0; half < 2; half++) {
                    float bv = -3.0e38f; int bc = 0;
#pragma unroll
                    for (int j = 0; j < 4; j++) {
                        float2 fv = __half22float2(
                            *reinterpret_cast<const __half2*>(&acc[i][j][half]));
                        const int c0 = colbase + j * 8;
                        if (fv.x > bv) { bv = fv.x; bc = c0; }
                        if (fv.y > bv) { bv = fv.y; bc = c0 + 1; }
                    }
#pragma unroll
                    for (int off = 1; off < 4; off <<= 1) {
                        float ov = __shfl_xor_sync(~0u, bv, off);
                        int   oc = __shfl_xor_sync(~0u, bc, off);
                        if (ov > bv || (ov == bv && oc < bc)) { bv = ov; bc = oc; }
                    }
                    if ((lane & 3) == 0) {
                        const int rloc = wm * 64 + i * 16 + half * 8 + (lane >> 2);
                        atomicMax(&table[rloc], packsc(bv, bc));
                    }
                }
            __syncthreads();
            // merge with global running row max -> cut
            if (tid < 128) {
                unsigned long long loc = table[tid];
                unsigned long long old = atomicMax(&g_gmax[qrow0 + tid], loc);
                if (old > loc) loc = old;
                tableF[tid] = unpack_score(loc) - MARGIN;
            }
            __syncthreads();
            // phase 2: append candidates >= cut
#pragma unroll
            for (int i = 0; i < 4; i++)
#pragma unroll
                for (int half = 0; half < 2; half++) {
                    const int rloc = wm * 64 + i * 16 + half * 8 + (lane >> 2);
                    const float cut = tableF[rloc];
                    const int rg = qrow0 + rloc;
#pragma unroll
                    for (int j = 0; j < 4; j++) {
                        float2 fv = __half22float2(
                            *reinterpret_cast<const __half2*>(&acc[i][j][half]));
                        if (fv.x >= cut) {
                            int slot = atomicAdd(&g_cnt[rg], 1);
                            if (slot < CAP)
                                g_cand[(size_t)rg * CAP + slot] = colbase + j * 8;
                        }
                        if (fv.y >= cut) {
                            int slot = atomicAdd(&g_cnt[rg], 1);
                            if (slot < CAP)
                                g_cand[(size_t)rg * CAP + slot] = colbase + j * 8 + 1;
                        }
                    }
                }
            __syncthreads();
            if (tid < 128) table[tid] = 0ull;
            // next table use is >= 12 chunks away, separated by syncs.
#pragma unroll
            for (int i = 0; i < 4; i++)
#pragma unroll
                for (int j = 0; j < 4; j++) { acc[i][j][0] = 0u; acc[i][j][1] = 0u; }
        }
    }
}

// ---------------------------------------------------------------------------
// Exact rescore + blend (per half): warp per row. grid HB*NN/8 blocks.
// out layout: [reuse_map (B*N)] [reuse_input (B*N*D)] [reuse_value (B*N*D)]
// ---------------------------------------------------------------------------
__global__ __launch_bounds__(256) void rescore_blend_kernel(
    const float* __restrict__ Qi, const float* __restrict__ Qv,
    const float* __restrict__ Ci, const float* __restrict__ Cv,
    const float* __restrict__ thr_raw, float* __restrict__ out, int b0) {
    const int r = b0 * NN + blockIdx.x * 8 + (threadIdx.x >> 5);
    const int lane = threadIdx.x & 31;
    const int b = r >> 11;
    const int n = r & (NN - 1);

    const float4* q4p = (const float4*)(Qi + (size_t)r * DD);
    float4 q4[6];
#pragma unroll
    for (int q = 0; q < 6; q++) q4[q] = q4p[lane + 32 * q];

    int cnt = g_cnt[r]; if (cnt > CAP) cnt = CAP;
    const float invq = g_invq[r];
    unsigned long long best = 0ull;
    for (int ci = 0; ci < cnt; ci++) {
        const int idx = g_cand[(size_t)r * CAP + ci];
        const float4* crow = (const float4*)(Ci + ((size_t)(b * NN + idx)) * DD);
        float s = 0.f;
#pragma unroll
        for (int q = 0; q < 6; q++) {
            float4 cv = crow[lane + 32 * q];
            s += cv.x * q4[q].x + cv.y * q4[q].y + cv.z * q4[q].z + cv.w * q4[q].w;
        }
#pragma unroll
        for (int o = 16; o > 0; o >>= 1) s += __shfl_xor_sync(~0u, s, o);
        unsigned long long p = packsc(s * invq * g_invc[b * NN + idx], idx);
        if (p > best) best = p;       // identical on all lanes
    }
    const float score = unpack_score(best);
    const int idx = 2047 - (int)(uint32_t)(best & 0xFFFFFFFFull);
    const float thr = 1.f / (1.f + expf(-thr_raw[n]));
    const float rm  = 1.f / (1.f + expf(-40.f * (score - thr)));
    const float om  = 1.f - rm;

    const float4* qv = (const float4*)(Qv + (size_t)r * DD);
    const float4* cb = (const float4*)(Ci + ((size_t)b * NN + idx) * DD);
    const float4* cv = (const float4*)(Cv + ((size_t)b * NN + idx) * DD);
    float4* oi = (float4*)(out + ROWS + (size_t)r * DD);
    float4* ov = (float4*)(out + ROWS + (size_t)ROWS * DD + (size_t)r * DD);
#pragma unroll
    for (int q = 0; q < 6; q++) {
        const int e = lane + 32 * q;
        float4 a = q4[q], c = cb[e];
        oi[e] = make_float4(om * a.x + rm * c.x, om * a.y + rm * c.y,
                            om * a.z + rm * c.z, om * a.w + rm * c.w);
        float4 av = qv[e], cc = cv[e];
        ov[e] = make_float4(om * av.x + rm * cc.x, om * av.y + rm * cc.y,
                            om * av.z + rm * cc.z, om * av.w + rm * cc.w);
    }
    if (lane == 0) out[r] = rm;
}

// ---------------------------------------------------------------------------
// Host: half-granular software pipeline via fork/join events.
// prep(h1) overlaps gemm(h0); rescore(h0) overlaps gemm(h1).
// ---------------------------------------------------------------------------
static cudaStream_t sP = nullptr, sR = nullptr;
static cudaEvent_t  eFork, eJoin, eP0, eP1, eG0, eG1;

extern "C" void kernel_launch(void* const* d_in, const int* in_sizes, int n_in,
                              void* d_out, int out_size) {
    const float* Qi = (const float*)d_in[0];
    const float* Qv = (const float*)d_in[1];
    const float* Ci = (const float*)d_in[2];
    const float* Cv = (const float*)d_in[3];
    const float* Th = (const float*)d_in[4];
    float* out = (float*)d_out;

    if (sP == nullptr) {
        cudaStreamCreateWithFlags(&sP, cudaStreamNonBlocking);
        cudaStreamCreateWithFlags(&sR, cudaStreamNonBlocking);
        cudaEventCreateWithFlags(&eFork, cudaEventDisableTiming);
        cudaEventCreateWithFlags(&eJoin, cudaEventDisableTiming);
        cudaEventCreateWithFlags(&eP0, cudaEventDisableTiming);
        cudaEventCreateWithFlags(&eP1, cudaEventDisableTiming);
        cudaEventCreateWithFlags(&eG0, cudaEventDisableTiming);
        cudaEventCreateWithFlags(&eG1, cudaEventDisableTiming);
        cudaFuncSetAttribute(gemm_kernel,
                             cudaFuncAttributeMaxDynamicSharedMemorySize, SMEM_DYN);
    }

    cudaEventRecord(eFork, 0);
    cudaStreamWaitEvent(sP, eFork, 0);

    // prep halves on sP
    prep_kernel<<<(2 * HB * NN) / 8, 256, 0, sP>>>(Qi, Ci, 0);
    cudaEventRecord(eP0, sP);
    prep_kernel<<<(2 * HB * NN) / 8, 256, 0, sP>>>(Qi, Ci, HB);
    cudaEventRecord(eP1, sP);

    // gemm halves on main
    cudaStreamWaitEvent(0, eP0, 0);
    gemm_kernel<<<GRID, 256, SMEM_DYN>>>(0);
    cudaEventRecord(eG0, 0);
    cudaStreamWaitEvent(0, eP1, 0);
    gemm_kernel<<<GRID, 256, SMEM_DYN>>>(HB);
    cudaEventRecord(eG1, 0);

    // rescore halves on sR
    cudaStreamWaitEvent(sR, eG0, 0);
    rescore_blend_kernel<<<(HB * NN) / 8, 256, 0, sR>>>(Qi, Qv, Ci, Cv, Th, out, 0);
    cudaStreamWaitEvent(sR, eG1, 0);
    rescore_blend_kernel<<<(HB * NN) / 8, 256, 0, sR>>>(Qi, Qv, Ci, Cv, Th, out, HB);
    cudaEventRecord(eJoin, sR);
    cudaStreamWaitEvent(0, eJoin, 0);
}